// round 5
// baseline (speedup 1.0000x reference)
#include <cuda_runtime.h>
#include <cuda_bf16.h>

// Problem constants (reference: B=16384, L=512, 3 channels interleaved)
#define L_SEQ      512
#define NTHREADS   128            // 4 positions per thread
#define PPT        (L_SEQ / NTHREADS)
#define PAD_STANCE 3.0f
#define GRID       1776           // 148 SMs x 12 CTAs -> single wave

// Pads are a strict suffix and valid stance is never 3.0, so
// cumprod(stance != PAD) == (stance != PAD) elementwise.

__global__ __launch_bounds__(NTHREADS, 12)
void crowd_kernel(const float* __restrict__ in,   // (B, 512, 3) fp32
                  const float* __restrict__ w,    // (1e6,) fp32
                  float* __restrict__ out,        // (6*B,) fp32: pre | dist | theta
                  int B)
{
    const int tid  = threadIdx.x;
    const int lane = tid & 31;
    const int wrp  = tid >> 5;

    // Static ceil-split of rows over the fixed grid (single wave).
    const int rpb = (B + GRID - 1) / GRID;
    const int r0  = blockIdx.x * rpb;
    const int r1  = min(B, r0 + rpb);
    if (r0 >= r1) return;

    // Double-buffered cross-warp partials: [parity][{real,fake,cnt}][warp]
    __shared__ float s_red[2][3][NTHREADS / 32];

    // ---- Prefetch row r0 (3 coalesced float4 per thread = whole row) ----
    const float4* src = reinterpret_cast<const float4*>(in)
                        + (size_t)r0 * (3 * NTHREADS) + 3 * tid;
    float4 v0 = src[0];
    float4 v1 = src[1];
    float4 v2 = src[2];

    for (int r = r0; r < r1; ++r) {
        // Demux interleaved (stance, col1, uid) for this thread's 4 positions.
        float st[PPT], uf[PPT];
        st[0] = v0.x;  uf[0] = v0.z;
        st[1] = v0.w;  uf[1] = v1.y;
        st[2] = v1.z;  uf[2] = v2.x;
        st[3] = v2.y;  uf[3] = v2.w;

        // ---- Issue NEXT row's stream loads immediately (depth-1 prefetch).
        // Their DRAM latency is covered by this row's gathers+reduce+barrier.
        if (r + 1 < r1) {
            const float4* nsrc = reinterpret_cast<const float4*>(in)
                                 + (size_t)(r + 1) * (3 * NTHREADS) + 3 * tid;
            v0 = nsrc[0];
            v1 = nsrc[1];
            v2 = nsrc[2];
        }

        // ---- Exact-predicated gathers (valid positions only). ----
        float uw[PPT];
        bool  val[PPT];
        #pragma unroll
        for (int k = 0; k < PPT; k++) {
            val[k] = (st[k] != PAD_STANCE);
            uw[k]  = val[k] ? __ldg(&w[(int)uf[k]]) : 0.0f;
        }

        // Per-thread accumulation: real/fake sums + valid count.
        float rp = 0.0f, fq = 0.0f, cn = 0.0f;
        #pragma unroll
        for (int k = 0; k < PPT; k++) {
            if (val[k]) {
                cn += 1.0f;
                if (st[k] == 0.0f) rp += uw[k];
                else               fq += uw[k];
            }
        }

        // Warp reduction (shared shuffle ladder).
        #pragma unroll
        for (int off = 16; off > 0; off >>= 1) {
            rp += __shfl_xor_sync(0xFFFFFFFFu, rp, off);
            fq += __shfl_xor_sync(0xFFFFFFFFu, fq, off);
            cn += __shfl_xor_sync(0xFFFFFFFFu, cn, off);
        }

        const int par = r & 1;
        if (lane == 0) {
            s_red[par][0][wrp] = rp;
            s_red[par][1][wrp] = fq;
            s_red[par][2][wrp] = cn;
        }
        __syncthreads();   // one barrier per row; parity buffer protects reuse

        // ---- Epilogue: softmax + Beta moments (thread 0). Other warps
        // proceed into the next iteration's loads while this runs.
        if (tid == 0) {
            float R = s_red[par][0][0] + s_red[par][0][1] + s_red[par][0][2] + s_red[par][0][3];
            float F = s_red[par][1][0] + s_red[par][1][1] + s_red[par][1][2] + s_red[par][1][3];
            float n = s_red[par][2][0] + s_red[par][2][1] + s_red[par][2][2] + s_red[par][2][3];

            float m   = fmaxf(R, F);
            float e0  = __expf(R - m);
            float e1  = __expf(F - m);
            float inv = 1.0f / (e0 + e1);
            float pre0 = e0 * inv;              // user_pre[:,0] (real)
            float pre1 = e1 * inv;              // user_pre[:,1] (fake)

            float th0 = pre0 * n;               // user_theta[:,0] -> beta_b
            float th1 = pre1 * n;               // user_theta[:,1] -> beta_a
            float a = th1, bb = th0;
            float s = a + bb;
            float mean = a / s;
            float var  = (a * bb) / (s * s * (s + 1.0f));

            // Output layout: tuple-flatten (user_pre, user_distribution, user_theta)
            out[(size_t)r * 2 + 0]                 = pre0;
            out[(size_t)r * 2 + 1]                 = pre1;
            out[(size_t)2 * B + (size_t)r * 2 + 0] = mean;
            out[(size_t)2 * B + (size_t)r * 2 + 1] = sqrtf(var);
            out[(size_t)4 * B + (size_t)r * 2 + 0] = th0;
            out[(size_t)4 * B + (size_t)r * 2 + 1] = th1;
        }
    }
}

extern "C" void kernel_launch(void* const* d_in, const int* in_sizes, int n_in,
                              void* d_out, int out_size)
{
    const float* in = (const float*)d_in[0];   // (B, 512, 3) fp32
    const float* w  = (const float*)d_in[1];   // (1e6,) fp32
    float* out = (float*)d_out;

    int B = in_sizes[0] / (L_SEQ * 3);

    crowd_kernel<<<GRID, NTHREADS>>>(in, w, out, B);
}